// round 1
// baseline (speedup 1.0000x reference)
#include <cuda_runtime.h>
#include <math.h>

#define BATCH 8
#define NHALF 2048
#define N2 4096
#define D 64
#define CAP 256
#define LALPHA 0.2f

// ---------------- scratch (static device globals; no allocation) ----------
__device__ float g_Wh[BATCH * N2 * D];   // 8 MB
__device__ float g_f[BATCH * N2];
__device__ float g_g[BATCH * N2];
__device__ int   g_cols[N2 * CAP];       // 4 MB CSR column indices
__device__ int   g_rowlen[N2];
__device__ float g_Fmax[BATCH * N2];     // per-column max of f over nonzero rows
__device__ float g_Z[BATCH * N2];        // per-column softmax denominator

__device__ __forceinline__ float lrelu(float x) { return x > 0.f ? x : LALPHA * x; }

__device__ __forceinline__ void atomicMaxF(float* addr, float val) {
    if (val >= 0.f) atomicMax((int*)addr, __float_as_int(val));
    else            atomicMin((unsigned int*)addr, __float_as_uint(val));
}

// ---------------- K0: init column stats -----------------------------------
__global__ void k_init() {
    int idx = blockIdx.x * blockDim.x + threadIdx.x;
    if (idx < BATCH * N2) { g_Fmax[idx] = -INFINITY; g_Z[idx] = 0.f; }
}

// ---------------- K1: Wh = concat(ht,h) @ W ; f = Wh@a1 ; g = Wh@a2 -------
__global__ void k_wh(const float* __restrict__ h, const float* __restrict__ ht,
                     const float* __restrict__ W, const float* __restrict__ a1,
                     const float* __restrict__ a2) {
    int i = blockIdx.x, b = blockIdx.y, o = threadIdx.x;  // blockDim = 64
    const float* src = (i < NHALF) ? (ht + ((size_t)b * NHALF + i) * D)
                                   : (h  + ((size_t)b * NHALF + (i - NHALF)) * D);
    __shared__ float hrow[D];
    hrow[o] = src[o];
    __syncthreads();
    float acc = 0.f;
    #pragma unroll
    for (int d = 0; d < D; d++) acc = fmaf(hrow[d], __ldg(&W[d * D + o]), acc);
    size_t row = (size_t)b * N2 + i;
    g_Wh[row * D + o] = acc;

    float v1 = acc * __ldg(&a1[o]);
    float v2 = acc * __ldg(&a2[o]);
    #pragma unroll
    for (int off = 16; off; off >>= 1) {
        v1 += __shfl_down_sync(0xffffffffu, v1, off);
        v2 += __shfl_down_sync(0xffffffffu, v2, off);
    }
    __shared__ float r1[2], r2[2];
    if ((o & 31) == 0) { r1[o >> 5] = v1; r2[o >> 5] = v2; }
    __syncthreads();
    if (o == 0) { g_f[row] = r1[0] + r1[1]; g_g[row] = r2[0] + r2[1]; }
}

// ---------------- K2: deterministic CSR build from adj --------------------
__global__ void k_csr(const float* __restrict__ adj) {
    int warp = threadIdx.x >> 5, lane = threadIdx.x & 31;
    int i = blockIdx.x * (blockDim.x >> 5) + warp;
    if (i >= N2) return;
    const float* arow = adj + (size_t)i * N2;
    int base = 0;
    for (int c0 = 0; c0 < N2; c0 += 32) {
        float v = arow[c0 + lane];
        unsigned m = __ballot_sync(0xffffffffu, v > 0.f);
        int pos = base + __popc(m & ((1u << lane) - 1u));
        if (v > 0.f && pos < CAP) g_cols[i * CAP + pos] = c0 + lane;
        base += __popc(m);
    }
    if (lane == 0) g_rowlen[i] = base < CAP ? base : CAP;
}

// ---------------- K3: column max of f over nonzero rows -------------------
__global__ void k_colmax() {
    int i = blockIdx.x;
    int len = g_rowlen[i];
    __shared__ int sj[CAP];
    __shared__ float f8[BATCH];
    for (int t = threadIdx.x; t < len; t += blockDim.x) sj[t] = g_cols[i * CAP + t];
    if (threadIdx.x < BATCH) f8[threadIdx.x] = g_f[(size_t)threadIdx.x * N2 + i];
    __syncthreads();
    int tot = len * BATCH;
    for (int idx = threadIdx.x; idx < tot; idx += blockDim.x) {
        int t = idx >> 3, b = idx & 7;
        atomicMaxF(&g_Fmax[(size_t)b * N2 + sj[t]], f8[b]);
    }
}

// ---------------- K4: column softmax denominators -------------------------
__global__ void k_colsum() {
    int i = blockIdx.x;
    int len = g_rowlen[i];
    __shared__ int sj[CAP];
    __shared__ float f8[BATCH];
    for (int t = threadIdx.x; t < len; t += blockDim.x) sj[t] = g_cols[i * CAP + t];
    if (threadIdx.x < BATCH) f8[threadIdx.x] = g_f[(size_t)threadIdx.x * N2 + i];
    __syncthreads();
    int tot = len * BATCH;
    for (int idx = threadIdx.x; idx < tot; idx += blockDim.x) {
        int t = idx >> 3, b = idx & 7;
        int j = sj[t];
        float gj = g_g[(size_t)b * N2 + j];
        float mj = lrelu(g_Fmax[(size_t)b * N2 + j] + gj);
        float s  = lrelu(f8[b] + gj);
        atomicAdd(&g_Z[(size_t)b * N2 + j], __expf(s - mj));
    }
}

// ---------------- K5: hp = att @ Wh (sparse), split channels, ELU ---------
__global__ void k_out(float* __restrict__ out) {
    int i = blockIdx.x, b = blockIdx.y, o = threadIdx.x;  // blockDim = 64
    int len = g_rowlen[i];
    __shared__ int sj[CAP];
    __shared__ float sw[CAP];
    float fi = g_f[(size_t)b * N2 + i];
    for (int t = o; t < len; t += D) sj[t] = g_cols[i * CAP + t];
    __syncthreads();
    for (int t = o; t < len; t += D) {
        int j = sj[t];
        float gj = g_g[(size_t)b * N2 + j];
        float mj = lrelu(g_Fmax[(size_t)b * N2 + j] + gj);
        float s  = lrelu(fi + gj);
        sw[t] = __expf(s - mj) / g_Z[(size_t)b * N2 + j];
    }
    __syncthreads();
    float acc = 0.f;
    const float* Whb = g_Wh + (size_t)b * N2 * D;
    #pragma unroll 4
    for (int t = 0; t < len; t++) {
        acc = fmaf(sw[t], Whb[(size_t)sj[t] * D + o], acc);
    }
    float v = acc > 0.f ? acc : expm1f(acc);   // ELU (expm1 avoids cancellation)
    int row = (i < NHALF) ? i : i - NHALF;
    int ch  = (i < NHALF) ? o : o + D;
    out[((size_t)b * NHALF + row) * (2 * D) + ch] = v;
}

// ---------------- launch ----------------------------------------------------
extern "C" void kernel_launch(void* const* d_in, const int* in_sizes, int n_in,
                              void* d_out, int out_size) {
    const float* h   = (const float*)d_in[0];
    const float* ht  = (const float*)d_in[1];
    const float* W   = (const float*)d_in[2];
    const float* a1  = (const float*)d_in[3];
    const float* a2  = (const float*)d_in[4];
    const float* adj = (const float*)d_in[5];
    float* out = (float*)d_out;

    k_init<<<(BATCH * N2 + 255) / 256, 256>>>();
    dim3 gridBN(N2, BATCH);
    k_wh<<<gridBN, D>>>(h, ht, W, a1, a2);
    k_csr<<<N2 / 8, 256>>>(adj);
    k_colmax<<<N2, 128>>>();
    k_colsum<<<N2, 128>>>();
    k_out<<<gridBN, D>>>(out);
}

// round 2
// speedup vs baseline: 1.3769x; 1.3769x over previous
#include <cuda_runtime.h>
#include <cuda_fp16.h>
#include <math.h>

#define BATCH 8
#define NHALF 2048
#define N2 4096
#define D 64
#define CAP 256
#define LALPHA 0.2f
#define WROWS 16

// ---------------- scratch (static device globals; no allocation) ----------
__device__ __half  g_Whh[BATCH * N2 * D];        // 4 MB  fp16 Wh
__device__ int     g_cols[N2 * CAP];             // 4 MB  CSR column indices
__device__ int     g_rowlen[N2];
__device__ int     g_csc[N2 * CAP];              // 4 MB  CSC row indices
__device__ int     g_cc[N2];                     // CSC counts
__device__ float4  g_rstat[BATCH * N2];          // (f, u=exp(f), p=exp(.2f), -)
__device__ float4  g_cstat[BATCH * N2];          // (g, v/Z, q/Z, -)

// ---------------- K0: zero CSC counters ------------------------------------
__global__ void k_init() {
    int idx = blockIdx.x * blockDim.x + threadIdx.x;
    if (idx < N2) g_cc[idx] = 0;
}

// ---------------- K1: Wh = concat(ht,h) @ W ; row/col stats ----------------
__global__ void k_wh(const float* __restrict__ h, const float* __restrict__ ht,
                     const float* __restrict__ W, const float* __restrict__ a1,
                     const float* __restrict__ a2) {
    int bx = blockIdx.x, b = blockIdx.y;
    int tx = threadIdx.x, ty = threadIdx.y;          // (64, 8)
    int tid = ty * 64 + tx;

    __shared__ float Ws[D * D];                      // 16 KB
    __shared__ float hr[WROWS][D];                   // 4 KB
    __shared__ float a1s[D], a2s[D];
    __shared__ float red1[8][2], red2[8][2];

    for (int k = tid; k < D * D; k += 512) Ws[k] = W[k];
    if (tid < D)            a1s[tid]      = a1[tid];
    else if (tid < 2 * D)   a2s[tid - D]  = a2[tid - D];

    int i0 = bx * WROWS;
    const float* src = (i0 < NHALF)
        ? (ht + ((size_t)b * NHALF + i0) * D)
        : (h  + ((size_t)b * NHALF + (i0 - NHALF)) * D);
    for (int k = tid; k < WROWS * D; k += 512) hr[k >> 6][k & 63] = src[k];
    __syncthreads();

    for (int rr = 0; rr < WROWS; rr += 8) {
        int r = rr + ty;
        float acc = 0.f;
        #pragma unroll
        for (int d = 0; d < D; d++) acc = fmaf(hr[r][d], Ws[d * D + tx], acc);

        int i = i0 + r;
        size_t row = (size_t)b * N2 + i;
        g_Whh[row * D + tx] = __float2half_rn(acc);

        float v1 = acc * a1s[tx];
        float v2 = acc * a2s[tx];
        #pragma unroll
        for (int off = 16; off; off >>= 1) {
            v1 += __shfl_down_sync(0xffffffffu, v1, off);
            v2 += __shfl_down_sync(0xffffffffu, v2, off);
        }
        if ((tx & 31) == 0) { red1[ty][tx >> 5] = v1; red2[ty][tx >> 5] = v2; }
        __syncthreads();
        if (tx == 0) {
            float f = red1[ty][0] + red1[ty][1];
            float g = red2[ty][0] + red2[ty][1];
            g_rstat[row] = make_float4(f, __expf(f), __expf(LALPHA * f), 0.f);
            g_cstat[row].x = g;
        }
        __syncthreads();
    }
}

// ---------------- K2: CSR build + CSC scatter -------------------------------
__global__ void k_csr(const float* __restrict__ adj) {
    int warp = threadIdx.x >> 5, lane = threadIdx.x & 31;
    int i = blockIdx.x * (blockDim.x >> 5) + warp;
    if (i >= N2) return;
    const float* arow = adj + (size_t)i * N2;
    int base = 0;
    #pragma unroll 4
    for (int c0 = 0; c0 < N2; c0 += 32) {
        float v = arow[c0 + lane];
        unsigned m = __ballot_sync(0xffffffffu, v > 0.f);
        int pos = base + __popc(m & ((1u << lane) - 1u));
        if (v > 0.f && pos < CAP) {
            int j = c0 + lane;
            g_cols[i * CAP + pos] = j;
            int p2 = atomicAdd(&g_cc[j], 1);
            if (p2 < CAP) g_csc[j * CAP + p2] = i;
        }
        base += __popc(m);
    }
    if (lane == 0) g_rowlen[i] = base < CAP ? base : CAP;
}

// ---------------- K3: per-column normalizers (no atomics, no per-elem exp) --
__global__ void k_Z() {
    int j = blockIdx.x;
    int tx = threadIdx.x, b = threadIdx.y;           // (32, 8)
    int tid = b * 32 + tx;
    int cl = g_cc[j]; if (cl > CAP) cl = CAP;

    __shared__ int si[CAP];
    for (int t = tid; t < cl; t += 256) si[t] = g_csc[j * CAP + t];
    __syncthreads();

    size_t bb = (size_t)b * N2;
    float gj = g_cstat[bb + j].x;
    float su = 0.f, sp = 0.f;
    for (int t = tx; t < cl; t += 32) {
        float4 r = g_rstat[bb + si[t]];
        if (r.x + gj > 0.f) su += r.y; else sp += r.z;
    }
    #pragma unroll
    for (int off = 16; off; off >>= 1) {
        su += __shfl_down_sync(0xffffffffu, su, off);
        sp += __shfl_down_sync(0xffffffffu, sp, off);
    }
    if (tx == 0) {
        float v = __expf(gj), q = __expf(LALPHA * gj);
        float Z = v * su + q * sp;
        float inv = 1.f / Z;                         // empty column -> inf, never read
        g_cstat[bb + j].y = v * inv;
        g_cstat[bb + j].z = q * inv;
    }
}

// ---------------- K4: hp = att @ Wh (sparse) + split + ELU ------------------
__global__ void k_out(float* __restrict__ out) {
    int i = blockIdx.x;
    int tx = threadIdx.x, b = threadIdx.y;           // (32, 8)
    int tid = b * 32 + tx;
    int len = g_rowlen[i];

    __shared__ int   sj[CAP];
    __shared__ float sw[BATCH][CAP];

    for (int t = tid; t < len; t += 256) sj[t] = g_cols[i * CAP + t];
    __syncthreads();

    size_t bb = (size_t)b * N2;
    float4 r = g_rstat[bb + i];
    float fi = r.x, ui = r.y, pi = r.z;

    for (int t = tx; t < len; t += 32) {
        float4 c = g_cstat[bb + sj[t]];
        sw[b][t] = (fi + c.x > 0.f) ? ui * c.y : pi * c.z;
    }
    __syncwarp();

    const __half2* Wb = (const __half2*)g_Whh + bb * (D / 2);
    float ax = 0.f, ay = 0.f;
    #pragma unroll 4
    for (int t = 0; t < len; t++) {
        float2 w = __half22float2(Wb[(size_t)sj[t] * (D / 2) + tx]);
        float s = sw[b][t];
        ax = fmaf(s, w.x, ax);
        ay = fmaf(s, w.y, ay);
    }

    float vx = ax > 0.f ? ax : expm1f(ax);
    float vy = ay > 0.f ? ay : expm1f(ay);
    int row = (i < NHALF) ? i : i - NHALF;
    int ch  = ((i < NHALF) ? 0 : D) + 2 * tx;
    *(float2*)&out[((size_t)b * NHALF + row) * (2 * D) + ch] = make_float2(vx, vy);
}

// ---------------- launch ----------------------------------------------------
extern "C" void kernel_launch(void* const* d_in, const int* in_sizes, int n_in,
                              void* d_out, int out_size) {
    const float* h   = (const float*)d_in[0];
    const float* ht  = (const float*)d_in[1];
    const float* W   = (const float*)d_in[2];
    const float* a1  = (const float*)d_in[3];
    const float* a2  = (const float*)d_in[4];
    const float* adj = (const float*)d_in[5];
    float* out = (float*)d_out;

    k_init<<<(N2 + 255) / 256, 256>>>();
    dim3 wgrid(N2 / WROWS, BATCH), wblk(64, 8);
    k_wh<<<wgrid, wblk>>>(h, ht, W, a1, a2);
    k_csr<<<N2 / 8, 256>>>(adj);
    dim3 blk328(32, 8);
    k_Z<<<N2, blk328>>>();
    k_out<<<N2, blk328>>>(out);
}